// round 14
// baseline (speedup 1.0000x reference)
#include <cuda_runtime.h>
#include <cuda_fp16.h>
#include <cstdint>

// ============================================================================
// PhaseCoherenceComputer: C[bh,q,k] = mean_h cos(phq - phk)
//   = (cos_q @ cos_k^T + sin_q @ sin_k^T) / 64
// 16 GEMMs [2048,128]@[128,2048]^T in fp16 (validated rel_err ~5.6e-5).
// 1/64 folded into A scratch. Scratch row (K=128 fp16): cos[0:64] sin[64:128].
// R14 = R13 (best gemm, 70.56us) + split-K prologue: two cp.async groups
// (k 0:64, k 64:128); MMA slices 0-3 start after the first half lands,
// overlapping the second half's arrival. One extra cheap 4-warp barrier.
// ============================================================================

#define NBH 16
#define SEQ 2048
#define NH  64
#define KS  128          // scratch K width (cos 64 | sin 64)
#define BM  128
#define BN  64

// ---------------- scratch (device globals; no allocation APIs) --------------
__device__ __align__(16) __half gA[NBH * SEQ * KS];   // 8 MB (pre-scaled 1/64)
__device__ __align__(16) __half gB[NBH * SEQ * KS];   // 8 MB

__device__ __forceinline__ uint32_t smem_u32(const void* p) {
    uint32_t a;
    asm("{ .reg .u64 t; cvta.to.shared.u64 t, %1; cvt.u32.u64 %0, t; }"
        : "=r"(a) : "l"(p));
    return a;
}

#define CP_ASYNC_16(smem, gptr)                                                \
    asm volatile("cp.async.cg.shared.global [%0], [%1], 16;"                   \
                 :: "r"(smem), "l"(gptr))
#define CP_COMMIT()  asm volatile("cp.async.commit_group;" ::: "memory")
#define CP_WAIT(N)   asm volatile("cp.async.wait_group %0;" :: "n"(N) : "memory")

#define LDSM_X4(r0, r1, r2, r3, addr)                                          \
    asm volatile("ldmatrix.sync.aligned.m8n8.x4.shared.b16 {%0,%1,%2,%3}, [%4];" \
                 : "=r"(r0), "=r"(r1), "=r"(r2), "=r"(r3) : "r"(addr))

#define MMA_F16(c0, c1, c2, c3, a0, a1, a2, a3, b0, b1)                        \
    asm volatile("mma.sync.aligned.m16n8k16.row.col.f32.f16.f16.f32 "          \
                 "{%0,%1,%2,%3}, {%4,%5,%6,%7}, {%8,%9}, {%0,%1,%2,%3};"       \
                 : "+f"(c0), "+f"(c1), "+f"(c2), "+f"(c3)                      \
                 : "r"(a0), "r"(a1), "r"(a2), "r"(a3), "r"(b0), "r"(b1))

#define STG_CS_V2(gptr, x, y)                                                  \
    asm volatile("st.global.cs.v2.f32 [%0], {%1,%2};"                          \
                 :: "l"(gptr), "f"(x), "f"(y) : "memory")

// ============================================================================
// Kernel 1: __sincosf -> fp16 scratch (A pre-scaled 1/NH). 4 harmonics/thread.
// ============================================================================
__global__ void phase_prep_kernel(const float* __restrict__ q,
                                  const float* __restrict__ k)
{
    const int NT = NBH * SEQ * (NH / 4);    // 524288 threads per tensor
    int idx = blockIdx.x * blockDim.x + threadIdx.x;
    if (idx >= 2 * NT) return;
    bool isQ = idx < NT;
    int li  = isQ ? idx : idx - NT;
    int row = li >> 4;
    int h4  = (li & 15) << 2;

    const float4 v = *(const float4*)((isQ ? q : k) + (size_t)row * NH + h4);
    const float sc = isQ ? (1.0f / (float)NH) : 1.0f;

    float s0, c0, s1, c1, s2, c2, s3, c3;
    __sincosf(v.x, &s0, &c0);
    __sincosf(v.y, &s1, &c1);
    __sincosf(v.z, &s2, &c2);
    __sincosf(v.w, &s3, &c3);

    __half2 ca = __floats2half2_rn(c0 * sc, c1 * sc);
    __half2 cb = __floats2half2_rn(c2 * sc, c3 * sc);
    __half2 sa = __floats2half2_rn(s0 * sc, s1 * sc);
    __half2 sb = __floats2half2_rn(s2 * sc, s3 * sc);

    __half* dst = (isQ ? gA : gB) + (size_t)row * KS;
    uint2 uc, us;
    uc.x = *reinterpret_cast<uint32_t*>(&ca);
    uc.y = *reinterpret_cast<uint32_t*>(&cb);
    us.x = *reinterpret_cast<uint32_t*>(&sa);
    us.y = *reinterpret_cast<uint32_t*>(&sb);
    *(uint2*)(dst + h4)      = uc;
    *(uint2*)(dst + 64 + h4) = us;
}

// ============================================================================
// Kernel 2: fp16 mma.sync GEMM. CTA tile 128x64, 128 threads (2x2 warps of
// 64x32). grid = (32,16,16) = 8192 CTAs. smem: A 32KB + B 16KB (256B rows,
// XOR swizzle). K loaded as two halves (k 0:64 / 64:128); slices 0-3 run on
// half 0 while half 1 arrives. Direct .cs scatter epilogue. 4 CTAs/SM.
// ============================================================================
#define A_BYTES (BM * 256)                    // 32768
#define B_BYTES (BN * 256)                    // 16384
#define SMEM_TOTAL (A_BYTES + B_BYTES)        // 49152

__global__ void __launch_bounds__(128, 4)
phase_gemm_kernel(float* __restrict__ out)
{
    extern __shared__ char smem[];
    const uint32_t sb = smem_u32(smem);
    const int tid  = threadIdx.x;
    const int wid  = tid >> 5;
    const int lane = tid & 31;
    const int wm   = wid >> 1;          // 0-1
    const int wn   = wid & 1;           // 0-1

    const int nt = blockIdx.x;          // 64-wide N tile
    const int mt = blockIdx.y;
    const int bh = blockIdx.z;

    const __half* __restrict__ pA = gA + ((size_t)bh * SEQ + (size_t)mt * BM) * KS;
    const __half* __restrict__ pB = gB + ((size_t)bh * SEQ + (size_t)nt * BN) * KS;

    // split-K copy mapping: rows of 256B = 16 chunks of 16B; half h covers
    // chunks h*8 .. h*8+7. thread -> row base r0 = tid>>3 (advances 16/iter,
    // multiple of 8 -> swizzle invariant), chunk c4 = tid&7 within the half.
    const int r0 = tid >> 3;             // 0-15
    const int c4 = tid & 7;
    const uint32_t swb = (uint32_t)(c4 ^ (r0 & 7));       // half-0 swizzle
    const uint32_t so_lo = (uint32_t)(r0 * 256) + (swb << 4);
    const uint32_t so_hi = (uint32_t)(r0 * 256) + ((8u | swb) << 4);
    const uint32_t go_lo = (uint32_t)(r0 * KS + c4 * 8);          // elements
    const uint32_t go_hi = go_lo + 64;

    // ---- group 0: k 0:64 of A (8 iters) + B (4 iters) ----
#pragma unroll
    for (int t = 0; t < 8; t++)
        CP_ASYNC_16(sb + so_lo + t * 4096, pA + go_lo + t * 2048);
#pragma unroll
    for (int t = 0; t < 4; t++)
        CP_ASYNC_16(sb + A_BYTES + so_lo + t * 4096, pB + go_lo + t * 2048);
    CP_COMMIT();
    // ---- group 1: k 64:128 ----
#pragma unroll
    for (int t = 0; t < 8; t++)
        CP_ASYNC_16(sb + so_hi + t * 4096, pA + go_hi + t * 2048);
#pragma unroll
    for (int t = 0; t < 4; t++)
        CP_ASYNC_16(sb + A_BYTES + so_hi + t * 4096, pB + go_hi + t * 2048);
    CP_COMMIT();

    // ldmatrix base rows
    const int rl = lane & 15;
    const int hc = lane >> 4;
    uint32_t aRow[4], bRow[2];
#pragma unroll
    for (int mf = 0; mf < 4; mf++) aRow[mf] = (uint32_t)(wm * 64 + mf * 16 + rl);
#pragma unroll
    for (int p = 0; p < 2; p++)   bRow[p]  = (uint32_t)(wn * 32 + p * 16 + rl);

    float acc[4][4][4];
#pragma unroll
    for (int mf = 0; mf < 4; mf++)
#pragma unroll
        for (int nf = 0; nf < 4; nf++)
#pragma unroll
            for (int j = 0; j < 4; j++) acc[mf][nf][j] = 0.0f;

    // ---- mainloop: slices 0-3 on half 0, then wait half 1 ----
#pragma unroll
    for (int kk = 0; kk < 8; kk++) {
        if (kk == 0) { CP_WAIT(1); __syncthreads(); }
        if (kk == 4) { CP_WAIT(0); __syncthreads(); }

        const uint32_t ch = (uint32_t)(kk * 2 + hc);   // 0-15
        uint32_t a[4][4];
#pragma unroll
        for (int mf = 0; mf < 4; mf++) {
            uint32_t r = aRow[mf];
            uint32_t sw = (ch & 8) | ((ch & 7) ^ (r & 7));
            LDSM_X4(a[mf][0], a[mf][1], a[mf][2], a[mf][3],
                    sb + r * 256 + (sw << 4));
        }
        uint32_t b[4][2];
#pragma unroll
        for (int p = 0; p < 2; p++) {
            uint32_t r = bRow[p];
            uint32_t sw = (ch & 8) | ((ch & 7) ^ (r & 7));
            uint32_t x0, x1, x2, x3;
            LDSM_X4(x0, x1, x2, x3, sb + A_BYTES + r * 256 + (sw << 4));
            b[p * 2][0]     = x0; b[p * 2][1]     = x2;
            b[p * 2 + 1][0] = x1; b[p * 2 + 1][1] = x3;
        }
#pragma unroll
        for (int mf = 0; mf < 4; mf++)
#pragma unroll
            for (int nf = 0; nf < 4; nf++)
                MMA_F16(acc[mf][nf][0], acc[mf][nf][1],
                        acc[mf][nf][2], acc[mf][nf][3],
                        a[mf][0], a[mf][1], a[mf][2], a[mf][3],
                        b[nf][0], b[nf][1]);
    }

    // ---- epilogue: direct .cs scatter (scale pre-folded into A) ----
    const int qg  = lane >> 2;
    const int cp2 = (lane & 3) * 2;
    float* obase = out + ((size_t)bh * SEQ + (size_t)mt * BM + wm * 64) * SEQ
                       + (size_t)nt * BN + wn * 32;
#pragma unroll
    for (int mf = 0; mf < 4; mf++) {
#pragma unroll
        for (int nf = 0; nf < 4; nf++) {
            float* p0 = obase + (size_t)(mf * 16 + qg) * SEQ + nf * 8 + cp2;
            STG_CS_V2(p0,           acc[mf][nf][0], acc[mf][nf][1]);
            STG_CS_V2(p0 + 8 * SEQ, acc[mf][nf][2], acc[mf][nf][3]);
        }
    }
}

// ============================================================================
// launch
// ============================================================================
extern "C" void kernel_launch(void* const* d_in, const int* in_sizes, int n_in,
                              void* d_out, int out_size)
{
    const float* q = (const float*)d_in[0];
    const float* k = (const float*)d_in[1];
    float* out = (float*)d_out;

    cudaFuncSetAttribute(phase_gemm_kernel,
                         cudaFuncAttributeMaxDynamicSharedMemorySize, SMEM_TOTAL);

    const int NT = NBH * SEQ * (NH / 4);
    int threads = 256;
    int blocks = (2 * NT + threads - 1) / threads;
    phase_prep_kernel<<<blocks, threads>>>(q, k);

    dim3 grid(SEQ / BN, SEQ / BM, NBH);   // (32,16,16)
    phase_gemm_kernel<<<grid, 128, SMEM_TOTAL>>>(out);
}

// round 15
// speedup vs baseline: 1.0193x; 1.0193x over previous
#include <cuda_runtime.h>
#include <cuda_fp16.h>
#include <cstdint>

// ============================================================================
// PhaseCoherenceComputer: C[bh,q,k] = mean_h cos(phq - phk)
//   = (cos_q @ cos_k^T + sin_q @ sin_k^T) / 64
// 16 GEMMs [2048,128]@[128,2048]^T in fp16 (validated rel_err ~5.6e-5).
// 1/64 folded into A scratch. Scratch row (K=128 fp16): cos[0:64] sin[64:128].
// R15 = R13 (proven best: 70.56us gemm / 73.95us total) reverted from R14's
// split-K (regressed). Only delta: B LDSMs issued before A LDSMs per slice.
// Session findings baked in: single wait+barrier, barrier-free mainloop,
// direct .cs scatter epilogue, 128-thread CTAs (4/SM), 16 warps/SM.
// ============================================================================

#define NBH 16
#define SEQ 2048
#define NH  64
#define KS  128          // scratch K width (cos 64 | sin 64)
#define BM  128
#define BN  64

// ---------------- scratch (device globals; no allocation APIs) --------------
__device__ __align__(16) __half gA[NBH * SEQ * KS];   // 8 MB (pre-scaled 1/64)
__device__ __align__(16) __half gB[NBH * SEQ * KS];   // 8 MB

__device__ __forceinline__ uint32_t smem_u32(const void* p) {
    uint32_t a;
    asm("{ .reg .u64 t; cvta.to.shared.u64 t, %1; cvt.u32.u64 %0, t; }"
        : "=r"(a) : "l"(p));
    return a;
}

#define CP_ASYNC_16(smem, gptr)                                                \
    asm volatile("cp.async.cg.shared.global [%0], [%1], 16;"                   \
                 :: "r"(smem), "l"(gptr))
#define CP_COMMIT()  asm volatile("cp.async.commit_group;" ::: "memory")
#define CP_WAIT(N)   asm volatile("cp.async.wait_group %0;" :: "n"(N) : "memory")

#define LDSM_X4(r0, r1, r2, r3, addr)                                          \
    asm volatile("ldmatrix.sync.aligned.m8n8.x4.shared.b16 {%0,%1,%2,%3}, [%4];" \
                 : "=r"(r0), "=r"(r1), "=r"(r2), "=r"(r3) : "r"(addr))

#define MMA_F16(c0, c1, c2, c3, a0, a1, a2, a3, b0, b1)                        \
    asm volatile("mma.sync.aligned.m16n8k16.row.col.f32.f16.f16.f32 "          \
                 "{%0,%1,%2,%3}, {%4,%5,%6,%7}, {%8,%9}, {%0,%1,%2,%3};"       \
                 : "+f"(c0), "+f"(c1), "+f"(c2), "+f"(c3)                      \
                 : "r"(a0), "r"(a1), "r"(a2), "r"(a3), "r"(b0), "r"(b1))

#define STG_CS_V2(gptr, x, y)                                                  \
    asm volatile("st.global.cs.v2.f32 [%0], {%1,%2};"                          \
                 :: "l"(gptr), "f"(x), "f"(y) : "memory")

// ============================================================================
// Kernel 1: __sincosf -> fp16 scratch (A pre-scaled 1/NH). 4 harmonics/thread.
// ============================================================================
__global__ void phase_prep_kernel(const float* __restrict__ q,
                                  const float* __restrict__ k)
{
    const int NT = NBH * SEQ * (NH / 4);    // 524288 threads per tensor
    int idx = blockIdx.x * blockDim.x + threadIdx.x;
    if (idx >= 2 * NT) return;
    bool isQ = idx < NT;
    int li  = isQ ? idx : idx - NT;
    int row = li >> 4;
    int h4  = (li & 15) << 2;

    const float4 v = *(const float4*)((isQ ? q : k) + (size_t)row * NH + h4);
    const float sc = isQ ? (1.0f / (float)NH) : 1.0f;

    float s0, c0, s1, c1, s2, c2, s3, c3;
    __sincosf(v.x, &s0, &c0);
    __sincosf(v.y, &s1, &c1);
    __sincosf(v.z, &s2, &c2);
    __sincosf(v.w, &s3, &c3);

    __half2 ca = __floats2half2_rn(c0 * sc, c1 * sc);
    __half2 cb = __floats2half2_rn(c2 * sc, c3 * sc);
    __half2 sa = __floats2half2_rn(s0 * sc, s1 * sc);
    __half2 sb = __floats2half2_rn(s2 * sc, s3 * sc);

    __half* dst = (isQ ? gA : gB) + (size_t)row * KS;
    uint2 uc, us;
    uc.x = *reinterpret_cast<uint32_t*>(&ca);
    uc.y = *reinterpret_cast<uint32_t*>(&cb);
    us.x = *reinterpret_cast<uint32_t*>(&sa);
    us.y = *reinterpret_cast<uint32_t*>(&sb);
    *(uint2*)(dst + h4)      = uc;
    *(uint2*)(dst + 64 + h4) = us;
}

// ============================================================================
// Kernel 2: fp16 mma.sync GEMM. CTA tile 128x64, 128 threads (2x2 warps of
// 64x32). grid = (32,16,16) = 8192 CTAs. smem: A 32KB + B 16KB (256B rows,
// XOR swizzle). All K loaded up-front, one wait+barrier, barrier-free
// mainloop, direct .cs scatter epilogue. 4 CTAs/SM.
// ============================================================================
#define A_BYTES (BM * 256)                    // 32768
#define B_BYTES (BN * 256)                    // 16384
#define SMEM_TOTAL (A_BYTES + B_BYTES)        // 49152

__global__ void __launch_bounds__(128, 4)
phase_gemm_kernel(float* __restrict__ out)
{
    extern __shared__ char smem[];
    const uint32_t sb = smem_u32(smem);
    const int tid  = threadIdx.x;
    const int wid  = tid >> 5;
    const int lane = tid & 31;
    const int wm   = wid >> 1;          // 0-1
    const int wn   = wid & 1;           // 0-1

    const int nt = blockIdx.x;          // 64-wide N tile
    const int mt = blockIdx.y;
    const int bh = blockIdx.z;

    const __half* __restrict__ pA = gA + ((size_t)bh * SEQ + (size_t)mt * BM) * KS;
    const __half* __restrict__ pB = gB + ((size_t)bh * SEQ + (size_t)nt * BN) * KS;

    // tile copy: rows of 256B = 16 chunks; idx = tid + t*128 -> row = idx>>4
    // (advances 8/t, multiple of 8 -> swizzle invariant), chunk c = tid&15.
    const int r0 = tid >> 4;             // 0-7
    const int c  = tid & 15;
    const uint32_t so0 = (uint32_t)(r0 * 256) +
                         ((uint32_t)((c & 8) | ((c & 7) ^ (r0 & 7))) << 4);
    const uint32_t go0 = (uint32_t)(r0 * KS + c * 8);   // elements

    // ---- load A (16 iters) + B (8 iters), single commit ----
#pragma unroll
    for (int t = 0; t < 16; t++)
        CP_ASYNC_16(sb + so0 + t * 2048, pA + go0 + t * 1024);
#pragma unroll
    for (int t = 0; t < 8; t++)
        CP_ASYNC_16(sb + A_BYTES + so0 + t * 2048, pB + go0 + t * 1024);
    CP_COMMIT();

    // ldmatrix base rows
    const int rl = lane & 15;
    const int hc = lane >> 4;
    uint32_t aRow[4], bRow[2];
#pragma unroll
    for (int mf = 0; mf < 4; mf++) aRow[mf] = (uint32_t)(wm * 64 + mf * 16 + rl);
#pragma unroll
    for (int p = 0; p < 2; p++)   bRow[p]  = (uint32_t)(wn * 32 + p * 16 + rl);

    float acc[4][4][4];
#pragma unroll
    for (int mf = 0; mf < 4; mf++)
#pragma unroll
        for (int nf = 0; nf < 4; nf++)
#pragma unroll
            for (int j = 0; j < 4; j++) acc[mf][nf][j] = 0.0f;

    // ---- single wait + 4-warp barrier, then barrier-free mainloop ----
    CP_WAIT(0);
    __syncthreads();

#pragma unroll
    for (int kk = 0; kk < 8; kk++) {
        const uint32_t ch = (uint32_t)(kk * 2 + hc);   // 0-15
        // B first: shorter dependency chain in flight earliest
        uint32_t b[4][2];
#pragma unroll
        for (int p = 0; p < 2; p++) {
            uint32_t r = bRow[p];
            uint32_t sw = (ch & 8) | ((ch & 7) ^ (r & 7));
            uint32_t x0, x1, x2, x3;
            LDSM_X4(x0, x1, x2, x3, sb + A_BYTES + r * 256 + (sw << 4));
            b[p * 2][0]     = x0; b[p * 2][1]     = x2;
            b[p * 2 + 1][0] = x1; b[p * 2 + 1][1] = x3;
        }
        uint32_t a[4][4];
#pragma unroll
        for (int mf = 0; mf < 4; mf++) {
            uint32_t r = aRow[mf];
            uint32_t sw = (ch & 8) | ((ch & 7) ^ (r & 7));
            LDSM_X4(a[mf][0], a[mf][1], a[mf][2], a[mf][3],
                    sb + r * 256 + (sw << 4));
        }
#pragma unroll
        for (int mf = 0; mf < 4; mf++)
#pragma unroll
            for (int nf = 0; nf < 4; nf++)
                MMA_F16(acc[mf][nf][0], acc[mf][nf][1],
                        acc[mf][nf][2], acc[mf][nf][3],
                        a[mf][0], a[mf][1], a[mf][2], a[mf][3],
                        b[nf][0], b[nf][1]);
    }

    // ---- epilogue: direct .cs scatter (scale pre-folded into A) ----
    const int qg  = lane >> 2;
    const int cp2 = (lane & 3) * 2;
    float* obase = out + ((size_t)bh * SEQ + (size_t)mt * BM + wm * 64) * SEQ
                       + (size_t)nt * BN + wn * 32;
#pragma unroll
    for (int mf = 0; mf < 4; mf++) {
#pragma unroll
        for (int nf = 0; nf < 4; nf++) {
            float* p0 = obase + (size_t)(mf * 16 + qg) * SEQ + nf * 8 + cp2;
            STG_CS_V2(p0,           acc[mf][nf][0], acc[mf][nf][1]);
            STG_CS_V2(p0 + 8 * SEQ, acc[mf][nf][2], acc[mf][nf][3]);
        }
    }
}

// ============================================================================
// launch
// ============================================================================
extern "C" void kernel_launch(void* const* d_in, const int* in_sizes, int n_in,
                              void* d_out, int out_size)
{
    const float* q = (const float*)d_in[0];
    const float* k = (const float*)d_in[1];
    float* out = (float*)d_out;

    cudaFuncSetAttribute(phase_gemm_kernel,
                         cudaFuncAttributeMaxDynamicSharedMemorySize, SMEM_TOTAL);

    const int NT = NBH * SEQ * (NH / 4);
    int threads = 256;
    int blocks = (2 * NT + threads - 1) / threads;
    phase_prep_kernel<<<blocks, threads>>>(q, k);

    dim3 grid(SEQ / BN, SEQ / BM, NBH);   // (32,16,16)
    phase_gemm_kernel<<<grid, 128, SMEM_TOTAL>>>(out);
}

// round 16
// speedup vs baseline: 1.0282x; 1.0087x over previous
#include <cuda_runtime.h>
#include <cuda_fp16.h>
#include <cstdint>

// ============================================================================
// PhaseCoherenceComputer: C[bh,q,k] = mean_h cos(phq - phk)
//   = (cos_q @ cos_k^T + sin_q @ sin_k^T) / 64
// 16 GEMMs [2048,128]@[128,2048]^T in fp16 (validated rel_err ~5.6e-5,
// 18x under the 1e-3 bar). 1/64 mean-scale folded into A scratch at prep.
// Scratch row (K=128 fp16): cos[0:64] | sin[64:128].
//
// FINAL (R16 = R13, session best: 70.56us gemm / 73.95us total):
//  - fp16 single-product via precision trade (vs bf16 hi/lo 3-product, 2.1x)
//  - 128-thread CTAs (2x2 warps of 64x32), 4 CTAs/SM, 16 warps/SM
//  - whole-K tile loaded up-front via cp.async, ONE wait + ONE 4-warp barrier
//  - barrier-free 8-slice mainloop (XOR-swizzled 256B smem rows, LDSM.x4)
//  - direct st.global.cs scatter epilogue (keeps L2 for the scratch tensors)
//  - __sincosf MUFU prep at its memory floor (~3.3us)
// Equilibrium: tensor 40% / L1 78% / DRAM 41% / issue 24% — invariant across
// 10 structural variants; the mma.sync issue equilibrium at 16 warps/SM.
// ============================================================================

#define NBH 16
#define SEQ 2048
#define NH  64
#define KS  128          // scratch K width (cos 64 | sin 64)
#define BM  128
#define BN  64

// ---------------- scratch (device globals; no allocation APIs) --------------
__device__ __align__(16) __half gA[NBH * SEQ * KS];   // 8 MB (pre-scaled 1/64)
__device__ __align__(16) __half gB[NBH * SEQ * KS];   // 8 MB

__device__ __forceinline__ uint32_t smem_u32(const void* p) {
    uint32_t a;
    asm("{ .reg .u64 t; cvta.to.shared.u64 t, %1; cvt.u32.u64 %0, t; }"
        : "=r"(a) : "l"(p));
    return a;
}

#define CP_ASYNC_16(smem, gptr)                                                \
    asm volatile("cp.async.cg.shared.global [%0], [%1], 16;"                   \
                 :: "r"(smem), "l"(gptr))
#define CP_COMMIT()  asm volatile("cp.async.commit_group;" ::: "memory")
#define CP_WAIT(N)   asm volatile("cp.async.wait_group %0;" :: "n"(N) : "memory")

#define LDSM_X4(r0, r1, r2, r3, addr)                                          \
    asm volatile("ldmatrix.sync.aligned.m8n8.x4.shared.b16 {%0,%1,%2,%3}, [%4];" \
                 : "=r"(r0), "=r"(r1), "=r"(r2), "=r"(r3) : "r"(addr))

#define MMA_F16(c0, c1, c2, c3, a0, a1, a2, a3, b0, b1)                        \
    asm volatile("mma.sync.aligned.m16n8k16.row.col.f32.f16.f16.f32 "          \
                 "{%0,%1,%2,%3}, {%4,%5,%6,%7}, {%8,%9}, {%0,%1,%2,%3};"       \
                 : "+f"(c0), "+f"(c1), "+f"(c2), "+f"(c3)                      \
                 : "r"(a0), "r"(a1), "r"(a2), "r"(a3), "r"(b0), "r"(b1))

#define STG_CS_V2(gptr, x, y)                                                  \
    asm volatile("st.global.cs.v2.f32 [%0], {%1,%2};"                          \
                 :: "l"(gptr), "f"(x), "f"(y) : "memory")

// ============================================================================
// Kernel 1: __sincosf -> fp16 scratch (A pre-scaled 1/NH). 4 harmonics/thread.
// ============================================================================
__global__ void phase_prep_kernel(const float* __restrict__ q,
                                  const float* __restrict__ k)
{
    const int NT = NBH * SEQ * (NH / 4);    // 524288 threads per tensor
    int idx = blockIdx.x * blockDim.x + threadIdx.x;
    if (idx >= 2 * NT) return;
    bool isQ = idx < NT;
    int li  = isQ ? idx : idx - NT;
    int row = li >> 4;
    int h4  = (li & 15) << 2;

    const float4 v = *(const float4*)((isQ ? q : k) + (size_t)row * NH + h4);
    const float sc = isQ ? (1.0f / (float)NH) : 1.0f;

    float s0, c0, s1, c1, s2, c2, s3, c3;
    __sincosf(v.x, &s0, &c0);
    __sincosf(v.y, &s1, &c1);
    __sincosf(v.z, &s2, &c2);
    __sincosf(v.w, &s3, &c3);

    __half2 ca = __floats2half2_rn(c0 * sc, c1 * sc);
    __half2 cb = __floats2half2_rn(c2 * sc, c3 * sc);
    __half2 sa = __floats2half2_rn(s0 * sc, s1 * sc);
    __half2 sb = __floats2half2_rn(s2 * sc, s3 * sc);

    __half* dst = (isQ ? gA : gB) + (size_t)row * KS;
    uint2 uc, us;
    uc.x = *reinterpret_cast<uint32_t*>(&ca);
    uc.y = *reinterpret_cast<uint32_t*>(&cb);
    us.x = *reinterpret_cast<uint32_t*>(&sa);
    us.y = *reinterpret_cast<uint32_t*>(&sb);
    *(uint2*)(dst + h4)      = uc;
    *(uint2*)(dst + 64 + h4) = us;
}

// ============================================================================
// Kernel 2: fp16 mma.sync GEMM. CTA tile 128x64, 128 threads (2x2 warps of
// 64x32). grid = (32,16,16) = 8192 CTAs. smem: A 32KB + B 16KB (256B rows,
// XOR swizzle). All K loaded up-front, one wait+barrier, barrier-free
// mainloop, direct .cs scatter epilogue. 4 CTAs/SM.
// ============================================================================
#define A_BYTES (BM * 256)                    // 32768
#define B_BYTES (BN * 256)                    // 16384
#define SMEM_TOTAL (A_BYTES + B_BYTES)        // 49152

__global__ void __launch_bounds__(128, 4)
phase_gemm_kernel(float* __restrict__ out)
{
    extern __shared__ char smem[];
    const uint32_t sb = smem_u32(smem);
    const int tid  = threadIdx.x;
    const int wid  = tid >> 5;
    const int lane = tid & 31;
    const int wm   = wid >> 1;          // 0-1
    const int wn   = wid & 1;           // 0-1

    const int nt = blockIdx.x;          // 64-wide N tile
    const int mt = blockIdx.y;
    const int bh = blockIdx.z;

    const __half* __restrict__ pA = gA + ((size_t)bh * SEQ + (size_t)mt * BM) * KS;
    const __half* __restrict__ pB = gB + ((size_t)bh * SEQ + (size_t)nt * BN) * KS;

    // tile copy: rows of 256B = 16 chunks; idx = tid + t*128 -> row = idx>>4
    // (advances 8/t, multiple of 8 -> swizzle invariant), chunk c = tid&15.
    const int r0 = tid >> 4;             // 0-7
    const int c  = tid & 15;
    const uint32_t so0 = (uint32_t)(r0 * 256) +
                         ((uint32_t)((c & 8) | ((c & 7) ^ (r0 & 7))) << 4);
    const uint32_t go0 = (uint32_t)(r0 * KS + c * 8);   // elements

    // ---- load A (16 iters) + B (8 iters), single commit ----
#pragma unroll
    for (int t = 0; t < 16; t++)
        CP_ASYNC_16(sb + so0 + t * 2048, pA + go0 + t * 1024);
#pragma unroll
    for (int t = 0; t < 8; t++)
        CP_ASYNC_16(sb + A_BYTES + so0 + t * 2048, pB + go0 + t * 1024);
    CP_COMMIT();

    // ldmatrix base rows
    const int rl = lane & 15;
    const int hc = lane >> 4;
    uint32_t aRow[4], bRow[2];
#pragma unroll
    for (int mf = 0; mf < 4; mf++) aRow[mf] = (uint32_t)(wm * 64 + mf * 16 + rl);
#pragma unroll
    for (int p = 0; p < 2; p++)   bRow[p]  = (uint32_t)(wn * 32 + p * 16 + rl);

    float acc[4][4][4];
#pragma unroll
    for (int mf = 0; mf < 4; mf++)
#pragma unroll
        for (int nf = 0; nf < 4; nf++)
#pragma unroll
            for (int j = 0; j < 4; j++) acc[mf][nf][j] = 0.0f;

    // ---- single wait + 4-warp barrier, then barrier-free mainloop ----
    CP_WAIT(0);
    __syncthreads();

#pragma unroll
    for (int kk = 0; kk < 8; kk++) {
        const uint32_t ch = (uint32_t)(kk * 2 + hc);   // 0-15
        uint32_t a[4][4];
#pragma unroll
        for (int mf = 0; mf < 4; mf++) {
            uint32_t r = aRow[mf];
            uint32_t sw = (ch & 8) | ((ch & 7) ^ (r & 7));
            LDSM_X4(a[mf][0], a[mf][1], a[mf][2], a[mf][3],
                    sb + r * 256 + (sw << 4));
        }
        uint32_t b[4][2];
#pragma unroll
        for (int p = 0; p < 2; p++) {
            uint32_t r = bRow[p];
            uint32_t sw = (ch & 8) | ((ch & 7) ^ (r & 7));
            uint32_t x0, x1, x2, x3;
            LDSM_X4(x0, x1, x2, x3, sb + A_BYTES + r * 256 + (sw << 4));
            b[p * 2][0]     = x0; b[p * 2][1]     = x2;
            b[p * 2 + 1][0] = x1; b[p * 2 + 1][1] = x3;
        }
#pragma unroll
        for (int mf = 0; mf < 4; mf++)
#pragma unroll
            for (int nf = 0; nf < 4; nf++)
                MMA_F16(acc[mf][nf][0], acc[mf][nf][1],
                        acc[mf][nf][2], acc[mf][nf][3],
                        a[mf][0], a[mf][1], a[mf][2], a[mf][3],
                        b[nf][0], b[nf][1]);
    }

    // ---- epilogue: direct .cs scatter (scale pre-folded into A) ----
    const int qg  = lane >> 2;
    const int cp2 = (lane & 3) * 2;
    float* obase = out + ((size_t)bh * SEQ + (size_t)mt * BM + wm * 64) * SEQ
                       + (size_t)nt * BN + wn * 32;
#pragma unroll
    for (int mf = 0; mf < 4; mf++) {
#pragma unroll
        for (int nf = 0; nf < 4; nf++) {
            float* p0 = obase + (size_t)(mf * 16 + qg) * SEQ + nf * 8 + cp2;
            STG_CS_V2(p0,           acc[mf][nf][0], acc[mf][nf][1]);
            STG_CS_V2(p0 + 8 * SEQ, acc[mf][nf][2], acc[mf][nf][3]);
        }
    }
}

// ============================================================================
// launch
// ============================================================================
extern "C" void kernel_launch(void* const* d_in, const int* in_sizes, int n_in,
                              void* d_out, int out_size)
{
    const float* q = (const float*)d_in[0];
    const float* k = (const float*)d_in[1];
    float* out = (float*)d_out;

    cudaFuncSetAttribute(phase_gemm_kernel,
                         cudaFuncAttributeMaxDynamicSharedMemorySize, SMEM_TOTAL);

    const int NT = NBH * SEQ * (NH / 4);
    int threads = 256;
    int blocks = (2 * NT + threads - 1) / threads;
    phase_prep_kernel<<<blocks, threads>>>(q, k);

    dim3 grid(SEQ / BN, SEQ / BM, NBH);   // (32,16,16)
    phase_gemm_kernel<<<grid, 128, SMEM_TOTAL>>>(out);
}

// round 17
// speedup vs baseline: 1.0286x; 1.0004x over previous
#include <cuda_runtime.h>
#include <cuda_fp16.h>
#include <cstdint>

// ============================================================================
// PhaseCoherenceComputer: C[bh,q,k] = mean_h cos(phq - phk)
//   = (cos_q @ cos_k^T + sin_q @ sin_k^T) / 64
// 16 GEMMs [2048,128]@[128,2048]^T in fp16 (validated rel_err ~5.6e-5,
// 18x under the 1e-3 bar). 1/64 mean-scale folded into A scratch at prep.
// Scratch row (K=128 fp16): cos[0:64] | sin[64:128].
//
// R17 = R16/R13 gemm (session best: 70.18us gemm / 73.82us total) unchanged
// + prep vectorized to 8 harmonics/thread (uint4 stores, half the issue).
//
// Architecture (findings baked in over 16 rounds):
//  - fp16 single-product via precision trade (vs bf16 hi/lo 3-product, 2.1x)
//  - 128-thread CTAs (2x2 warps of 64x32), 4 CTAs/SM, 16 warps/SM
//  - whole-K tile loaded up-front via cp.async, ONE wait + ONE 4-warp barrier
//  - barrier-free 8-slice mainloop (XOR-swizzled 256B smem rows, LDSM.x4)
//  - direct st.global.cs scatter epilogue (keeps L2 for the scratch tensors)
// Equilibrium: tensor 40% / L1 79% / DRAM 41% / issue 24% — invariant across
// 10 structural variants; the mma.sync issue equilibrium at 16 warps/SM.
// ============================================================================

#define NBH 16
#define SEQ 2048
#define NH  64
#define KS  128          // scratch K width (cos 64 | sin 64)
#define BM  128
#define BN  64

// ---------------- scratch (device globals; no allocation APIs) --------------
__device__ __align__(16) __half gA[NBH * SEQ * KS];   // 8 MB (pre-scaled 1/64)
__device__ __align__(16) __half gB[NBH * SEQ * KS];   // 8 MB

__device__ __forceinline__ uint32_t smem_u32(const void* p) {
    uint32_t a;
    asm("{ .reg .u64 t; cvta.to.shared.u64 t, %1; cvt.u32.u64 %0, t; }"
        : "=r"(a) : "l"(p));
    return a;
}

#define CP_ASYNC_16(smem, gptr)                                                \
    asm volatile("cp.async.cg.shared.global [%0], [%1], 16;"                   \
                 :: "r"(smem), "l"(gptr))
#define CP_COMMIT()  asm volatile("cp.async.commit_group;" ::: "memory")
#define CP_WAIT(N)   asm volatile("cp.async.wait_group %0;" :: "n"(N) : "memory")

#define LDSM_X4(r0, r1, r2, r3, addr)                                          \
    asm volatile("ldmatrix.sync.aligned.m8n8.x4.shared.b16 {%0,%1,%2,%3}, [%4];" \
                 : "=r"(r0), "=r"(r1), "=r"(r2), "=r"(r3) : "r"(addr))

#define MMA_F16(c0, c1, c2, c3, a0, a1, a2, a3, b0, b1)                        \
    asm volatile("mma.sync.aligned.m16n8k16.row.col.f32.f16.f16.f32 "          \
                 "{%0,%1,%2,%3}, {%4,%5,%6,%7}, {%8,%9}, {%0,%1,%2,%3};"       \
                 : "+f"(c0), "+f"(c1), "+f"(c2), "+f"(c3)                      \
                 : "r"(a0), "r"(a1), "r"(a2), "r"(a3), "r"(b0), "r"(b1))

#define STG_CS_V2(gptr, x, y)                                                  \
    asm volatile("st.global.cs.v2.f32 [%0], {%1,%2};"                          \
                 :: "l"(gptr), "f"(x), "f"(y) : "memory")

// ============================================================================
// Kernel 1: __sincosf -> fp16 scratch (A pre-scaled 1/NH). 8 harmonics/thread:
// two float4 loads, one uint4 store per trig type.
// ============================================================================
__global__ void phase_prep_kernel(const float* __restrict__ q,
                                  const float* __restrict__ k)
{
    const int NT8 = NBH * SEQ * (NH / 8);   // 262144 threads per tensor
    int idx = blockIdx.x * blockDim.x + threadIdx.x;
    if (idx >= 2 * NT8) return;
    bool isQ = idx < NT8;
    int li  = isQ ? idx : idx - NT8;
    int row = li >> 3;
    int h8  = (li & 7) << 3;

    const float* src = (isQ ? q : k) + (size_t)row * NH + h8;
    const float4 v0 = *(const float4*)(src);
    const float4 v1 = *(const float4*)(src + 4);
    const float sc = isQ ? (1.0f / (float)NH) : 1.0f;

    float s[8], c[8];
    __sincosf(v0.x, &s[0], &c[0]);
    __sincosf(v0.y, &s[1], &c[1]);
    __sincosf(v0.z, &s[2], &c[2]);
    __sincosf(v0.w, &s[3], &c[3]);
    __sincosf(v1.x, &s[4], &c[4]);
    __sincosf(v1.y, &s[5], &c[5]);
    __sincosf(v1.z, &s[6], &c[6]);
    __sincosf(v1.w, &s[7], &c[7]);

    uint4 uc, us;
    {
        __half2 h0 = __floats2half2_rn(c[0] * sc, c[1] * sc);
        __half2 h1 = __floats2half2_rn(c[2] * sc, c[3] * sc);
        __half2 h2 = __floats2half2_rn(c[4] * sc, c[5] * sc);
        __half2 h3 = __floats2half2_rn(c[6] * sc, c[7] * sc);
        uc.x = *reinterpret_cast<uint32_t*>(&h0);
        uc.y = *reinterpret_cast<uint32_t*>(&h1);
        uc.z = *reinterpret_cast<uint32_t*>(&h2);
        uc.w = *reinterpret_cast<uint32_t*>(&h3);
    }
    {
        __half2 h0 = __floats2half2_rn(s[0] * sc, s[1] * sc);
        __half2 h1 = __floats2half2_rn(s[2] * sc, s[3] * sc);
        __half2 h2 = __floats2half2_rn(s[4] * sc, s[5] * sc);
        __half2 h3 = __floats2half2_rn(s[6] * sc, s[7] * sc);
        us.x = *reinterpret_cast<uint32_t*>(&h0);
        us.y = *reinterpret_cast<uint32_t*>(&h1);
        us.z = *reinterpret_cast<uint32_t*>(&h2);
        us.w = *reinterpret_cast<uint32_t*>(&h3);
    }

    __half* dst = (isQ ? gA : gB) + (size_t)row * KS;
    *(uint4*)(dst + h8)      = uc;   // cos  -> cols h8..h8+7  (16B aligned)
    *(uint4*)(dst + 64 + h8) = us;   // sin  -> cols 64+h8..   (16B aligned)
}

// ============================================================================
// Kernel 2: fp16 mma.sync GEMM. CTA tile 128x64, 128 threads (2x2 warps of
// 64x32). grid = (32,16,16) = 8192 CTAs. smem: A 32KB + B 16KB (256B rows,
// XOR swizzle). All K loaded up-front, one wait+barrier, barrier-free
// mainloop, direct .cs scatter epilogue. 4 CTAs/SM.
// ============================================================================
#define A_BYTES (BM * 256)                    // 32768
#define B_BYTES (BN * 256)                    // 16384
#define SMEM_TOTAL (A_BYTES + B_BYTES)        // 49152

__global__ void __launch_bounds__(128, 4)
phase_gemm_kernel(float* __restrict__ out)
{
    extern __shared__ char smem[];
    const uint32_t sb = smem_u32(smem);
    const int tid  = threadIdx.x;
    const int wid  = tid >> 5;
    const int lane = tid & 31;
    const int wm   = wid >> 1;          // 0-1
    const int wn   = wid & 1;           // 0-1

    const int nt = blockIdx.x;          // 64-wide N tile
    const int mt = blockIdx.y;
    const int bh = blockIdx.z;

    const __half* __restrict__ pA = gA + ((size_t)bh * SEQ + (size_t)mt * BM) * KS;
    const __half* __restrict__ pB = gB + ((size_t)bh * SEQ + (size_t)nt * BN) * KS;

    // tile copy: rows of 256B = 16 chunks; idx = tid + t*128 -> row = idx>>4
    // (advances 8/t, multiple of 8 -> swizzle invariant), chunk c = tid&15.
    const int r0 = tid >> 4;             // 0-7
    const int c  = tid & 15;
    const uint32_t so0 = (uint32_t)(r0 * 256) +
                         ((uint32_t)((c & 8) | ((c & 7) ^ (r0 & 7))) << 4);
    const uint32_t go0 = (uint32_t)(r0 * KS + c * 8);   // elements

    // ---- load A (16 iters) + B (8 iters), single commit ----
#pragma unroll
    for (int t = 0; t < 16; t++)
        CP_ASYNC_16(sb + so0 + t * 2048, pA + go0 + t * 1024);
#pragma unroll
    for (int t = 0; t < 8; t++)
        CP_ASYNC_16(sb + A_BYTES + so0 + t * 2048, pB + go0 + t * 1024);
    CP_COMMIT();

    // ldmatrix base rows
    const int rl = lane & 15;
    const int hc = lane >> 4;
    uint32_t aRow[4], bRow[2];
#pragma unroll
    for (int mf = 0; mf < 4; mf++) aRow[mf] = (uint32_t)(wm * 64 + mf * 16 + rl);
#pragma unroll
    for (int p = 0; p < 2; p++)   bRow[p]  = (uint32_t)(wn * 32 + p * 16 + rl);

    float acc[4][4][4];
#pragma unroll
    for (int mf = 0; mf < 4; mf++)
#pragma unroll
        for (int nf = 0; nf < 4; nf++)
#pragma unroll
            for (int j = 0; j < 4; j++) acc[mf][nf][j] = 0.0f;

    // ---- single wait + 4-warp barrier, then barrier-free mainloop ----
    CP_WAIT(0);
    __syncthreads();

#pragma unroll
    for (int kk = 0; kk < 8; kk++) {
        const uint32_t ch = (uint32_t)(kk * 2 + hc);   // 0-15
        uint32_t a[4][4];
#pragma unroll
        for (int mf = 0; mf < 4; mf++) {
            uint32_t r = aRow[mf];
            uint32_t sw = (ch & 8) | ((ch & 7) ^ (r & 7));
            LDSM_X4(a[mf][0], a[mf][1], a[mf][2], a[mf][3],
                    sb + r * 256 + (sw << 4));
        }
        uint32_t b[4][2];
#pragma unroll
        for (int p = 0; p < 2; p++) {
            uint32_t r = bRow[p];
            uint32_t sw = (ch & 8) | ((ch & 7) ^ (r & 7));
            uint32_t x0, x1, x2, x3;
            LDSM_X4(x0, x1, x2, x3, sb + A_BYTES + r * 256 + (sw << 4));
            b[p * 2][0]     = x0; b[p * 2][1]     = x2;
            b[p * 2 + 1][0] = x1; b[p * 2 + 1][1] = x3;
        }
#pragma unroll
        for (int mf = 0; mf < 4; mf++)
#pragma unroll
            for (int nf = 0; nf < 4; nf++)
                MMA_F16(acc[mf][nf][0], acc[mf][nf][1],
                        acc[mf][nf][2], acc[mf][nf][3],
                        a[mf][0], a[mf][1], a[mf][2], a[mf][3],
                        b[nf][0], b[nf][1]);
    }

    // ---- epilogue: direct .cs scatter (scale pre-folded into A) ----
    const int qg  = lane >> 2;
    const int cp2 = (lane & 3) * 2;
    float* obase = out + ((size_t)bh * SEQ + (size_t)mt * BM + wm * 64) * SEQ
                       + (size_t)nt * BN + wn * 32;
#pragma unroll
    for (int mf = 0; mf < 4; mf++) {
#pragma unroll
        for (int nf = 0; nf < 4; nf++) {
            float* p0 = obase + (size_t)(mf * 16 + qg) * SEQ + nf * 8 + cp2;
            STG_CS_V2(p0,           acc[mf][nf][0], acc[mf][nf][1]);
            STG_CS_V2(p0 + 8 * SEQ, acc[mf][nf][2], acc[mf][nf][3]);
        }
    }
}

// ============================================================================
// launch
// ============================================================================
extern "C" void kernel_launch(void* const* d_in, const int* in_sizes, int n_in,
                              void* d_out, int out_size)
{
    const float* q = (const float*)d_in[0];
    const float* k = (const float*)d_in[1];
    float* out = (float*)d_out;

    cudaFuncSetAttribute(phase_gemm_kernel,
                         cudaFuncAttributeMaxDynamicSharedMemorySize, SMEM_TOTAL);

    const int NT8 = NBH * SEQ * (NH / 8);
    int threads = 256;
    int blocks = (2 * NT8 + threads - 1) / threads;
    phase_prep_kernel<<<blocks, threads>>>(q, k);

    dim3 grid(SEQ / BN, SEQ / BM, NBH);   // (32,16,16)
    phase_gemm_kernel<<<grid, 128, SMEM_TOTAL>>>(out);
}